// round 11
// baseline (speedup 1.0000x reference)
#include <cuda_runtime.h>
#include <cuda_bf16.h>
#include <cstdint>
#include <cstddef>

// ---------------- Problem constants ----------------
#define BATCH    16384
#define EMB      64
#define NSP      26
#define NFEAT    28            // user + item + 26 sparse
#define KDIM     1792
#define NDIM     128
#define SPVOC    100000
#define TILE_M   64
#define NTH      512           // 16 warps: kg(2) x rg(4) x nh(2)
#define NSTG     4             // A ring stages
#define A_ROW_B  160           // 128B data + 32B pad (2-way LDS conflicts max)
#define A_SLOT_B (16 * A_ROW_B)        // 2560 B per (kg,rg) stage
#define X_STR    132

#define OFF_A    0
#define SZ_A     (8 * NSTG * A_SLOT_B)           // 81920
#define OFF_IDX  SZ_A
#define SZ_IDX   (TILE_M * NFEAT * 4)            // 7168
#define OFF_PART (OFF_IDX + SZ_IDX)              // 89088
#define SMEM_TOTAL (OFF_PART + TILE_M * 2 * 4)   // 89600

// W1 pre-packed in mma B-fragment order:
// idx = ((((f*4 + kg*2+nh)*2 + kk)*8 + nt)*32 + lane)*2 + j
// val = pack_bf16(W1[k][n], W1[k+1][n]); n = nh*64+nt*8+(lane>>2);
// k = f*64 + kg*32 + kk*16 + (lane&3)*2 + j*8
__device__ uint32_t g_W1frag[NFEAT * 4 * 2 * 8 * 32 * 2];   // 448 KB

__global__ void prep_w1frag(const float* __restrict__ W1) {
    int i = blockIdx.x * blockDim.x + threadIdx.x;
    if (i >= NFEAT * 4096) return;
    int j    = i & 1;
    int lane = (i >> 1) & 31;
    int nt   = (i >> 6) & 7;
    int kk   = (i >> 9) & 1;
    int pgb  = (i >> 10) & 3;
    int f    = i >> 12;
    int kg = pgb >> 1, nh = pgb & 1;
    int n = nh * 64 + nt * 8 + (lane >> 2);
    int k = f * 64 + kg * 32 + kk * 16 + (lane & 3) * 2 + j * 8;
    __nv_bfloat162 h = __floats2bfloat162_rn(W1[(size_t)k * NDIM + n],
                                             W1[(size_t)(k + 1) * NDIM + n]);
    g_W1frag[i] = *(uint32_t*)&h;
}

// ---------------- PTX helpers ----------------
__device__ __forceinline__ void cpa16(uint32_t s, const void* g) {
    asm volatile("cp.async.cg.shared.global [%0], [%1], 16;\n" :: "r"(s), "l"(g));
}
__device__ __forceinline__ void cpa_commit() {
    asm volatile("cp.async.commit_group;\n" ::: "memory");
}
__device__ __forceinline__ void cpa_wait2() {
    asm volatile("cp.async.wait_group 2;\n" ::: "memory");
}
__device__ __forceinline__ void barx(int id) {
    asm volatile("bar.sync %0, 64;" :: "r"(id) : "memory");
}
__device__ __forceinline__ uint32_t lds_pack(uint32_t addr) {   // fp32x2 -> bf16x2
    float x, y;
    asm volatile("ld.shared.v2.f32 {%0,%1}, [%2];" : "=f"(x), "=f"(y) : "r"(addr));
    __nv_bfloat162 h = __floats2bfloat162_rn(x, y);
    return *(uint32_t*)&h;
}

__global__ __launch_bounds__(NTH, 2) void dlrm_fused_kernel(
    const int*   __restrict__ user_ids,
    const int*   __restrict__ item_ids,
    const int*   __restrict__ sparse,
    const float* __restrict__ user_emb,
    const float* __restrict__ item_emb,
    const float* __restrict__ sparse_tables,
    const float* __restrict__ b1,
    const float* __restrict__ W2,
    const float* __restrict__ b2,
    float*       __restrict__ out)
{
    extern __shared__ __align__(16) char smem_raw[];
    int*   sIdx  = (int*)(smem_raw + OFF_IDX);
    float* sPart = (float*)(smem_raw + OFF_PART);
    float* sX    = (float*)(smem_raw + OFF_A);    // reused post-mainloop

    const uint32_t sb = (uint32_t)__cvta_generic_to_shared(smem_raw);

    const int tid  = threadIdx.x;
    const int warp = tid >> 5;
    const int lane = tid & 31;
    const int row0 = blockIdx.x * TILE_M;

    const int g   = lane >> 2;          // 0..7
    const int tg  = lane & 3;           // 0..3
    const int kg  = warp >> 3;          // k half (2 k16-steps each)
    const int rg  = (warp >> 1) & 3;    // row group (16 rows)
    const int nh  = warp & 1;           // n half (64 cols)
    const int pga = kg * 4 + rg;        // A share group (nh-pair)
    const int pgb = kg * 2 + nh;        // B fragment page

    const uint32_t aGrp = sb + OFF_A + pga * (NSTG * A_SLOT_B);

    // ---- Preload all 64x28 indices into SMEM (one round trip)
    #pragma unroll
    for (int j = 0; j < 4; ++j) {
        int linear = tid + j * NTH;          // < 2048
        if (linear < TILE_M * NFEAT) {
            int r = linear / NFEAT;
            int f = linear - r * NFEAT;
            int v;
            if (f == 0)      v = __ldg(user_ids + row0 + r);
            else if (f == 1) v = __ldg(item_ids + row0 + r);
            else             v = __ldg(sparse + (size_t)(row0 + r) * NSP + (f - 2));
            sIdx[r * NFEAT + f] = v;
        }
    }
    __syncthreads();

    // accumulators: 8 n-tiles x 4 (1 m-tile of 16 rows, K-half partials)
    float c[8][4];
    #pragma unroll
    for (int nt = 0; nt < 8; ++nt) {
        c[nt][0] = 0.f; c[nt][1] = 0.f; c[nt][2] = 0.f; c[nt][3] = 0.f;
    }

    // ---- per-feature A cp.async: the nh-pair (64 thr) fills its (kg,rg) slot
    //      16 rows x 128B (k-half) = 128 x 16B chunks, 2 per thread
    const int pairLane = nh * 32 + lane;     // 0..63 within pair
    auto cpa_feat = [&](int f) {
        const uint32_t aslot = aGrp + (f & (NSTG - 1)) * A_SLOT_B;
        #pragma unroll
        for (int i = 0; i < 2; ++i) {
            int cch = pairLane + i * 64;     // 0..127
            int r16 = cch >> 3;              // 0..15
            int ch  = cch & 7;               // 16B chunk in 128B half-row
            int idx = sIdx[(rg * 16 + r16) * NFEAT + f];
            const float* src;
            if (f == 0)      src = user_emb + (size_t)idx * EMB;
            else if (f == 1) src = item_emb + (size_t)idx * EMB;
            else             src = sparse_tables + ((size_t)(f - 2) * SPVOC + (size_t)idx) * EMB;
            cpa16(aslot + r16 * A_ROW_B + ch * 16, src + kg * 32 + ch * 4);
        }
    };

    // ---- prologue: 3 features in flight
    cpa_feat(0); cpa_commit();
    cpa_feat(1); cpa_commit();
    cpa_feat(2); cpa_commit();

    // ---- mainloop: pairwise named barriers only, B streamed via __ldg
    #pragma unroll 1
    for (int f = 0; f < NFEAT; ++f) {
        cpa_wait2();                   // my stage-f copies arrived
        barx(1 + pga);                 // sibling's arrived too; its f-1 reads done
        if (f + 3 < NFEAT) cpa_feat(f + 3);
        cpa_commit();                  // uniform group cadence

        const uint32_t aslot = aGrp + (f & (NSTG - 1)) * A_SLOT_B;
        const uint32_t* bpage = g_W1frag + (size_t)((f * 4 + pgb) * 2) * 512;

        #pragma unroll
        for (int kk = 0; kk < 2; ++kk) {
            uint32_t a0r = aslot + g * A_ROW_B + kk * 64 + tg * 8;
            uint32_t a1r = a0r + 8 * A_ROW_B;
            uint32_t a0 = lds_pack(a0r);
            uint32_t a1 = lds_pack(a1r);
            uint32_t a2 = lds_pack(a0r + 32);
            uint32_t a3 = lds_pack(a1r + 32);
            const uint32_t* bk = bpage + kk * 512 + lane * 2;
            #pragma unroll
            for (int nt = 0; nt < 8; ++nt) {
                uint2 b = __ldg((const uint2*)(bk + nt * 64));
                asm volatile(
                    "mma.sync.aligned.m16n8k16.row.col.f32.bf16.bf16.f32 "
                    "{%0,%1,%2,%3}, {%4,%5,%6,%7}, {%8,%9}, {%0,%1,%2,%3};\n"
                    : "+f"(c[nt][0]), "+f"(c[nt][1]),
                      "+f"(c[nt][2]), "+f"(c[nt][3])
                    : "r"(a0), "r"(a1), "r"(a2), "r"(a3),
                      "r"(b.x), "r"(b.y));
            }
        }
    }

    // ---- K-group reduction (ReLU needs full sum): kg1 stores, kg0 reduces
    __syncthreads();                  // all A-ring reads done; reuse as sX
    if (kg == 1) {
        #pragma unroll
        for (int nt = 0; nt < 8; ++nt) {
            int r0l = rg * 16 + g;
            int col = nh * 64 + nt * 8 + 2 * tg;
            sX[r0l * X_STR + col]           = c[nt][0];
            sX[r0l * X_STR + col + 1]       = c[nt][1];
            sX[(r0l + 8) * X_STR + col]     = c[nt][2];
            sX[(r0l + 8) * X_STR + col + 1] = c[nt][3];
        }
    }
    __syncthreads();

    if (kg == 0) {
        float acc0 = 0.f, acc1 = 0.f;
        int r0l = rg * 16 + g;
        #pragma unroll
        for (int nt = 0; nt < 8; ++nt) {
            int n0 = nh * 64 + nt * 8 + 2 * tg;
            float h0 = c[nt][0] + sX[r0l * X_STR + n0];
            float h1 = c[nt][1] + sX[r0l * X_STR + n0 + 1];
            float h2 = c[nt][2] + sX[(r0l + 8) * X_STR + n0];
            float h3 = c[nt][3] + sX[(r0l + 8) * X_STR + n0 + 1];
            float bias0 = __ldg(b1 + n0);
            float bias1 = __ldg(b1 + n0 + 1);
            float w0 = __ldg(W2 + n0);
            float w1 = __ldg(W2 + n0 + 1);
            acc0 += fmaxf(h0 + bias0, 0.f) * w0;
            acc0 += fmaxf(h1 + bias1, 0.f) * w1;
            acc1 += fmaxf(h2 + bias0, 0.f) * w0;
            acc1 += fmaxf(h3 + bias1, 0.f) * w1;
        }
        acc0 += __shfl_xor_sync(0xffffffffu, acc0, 1);
        acc0 += __shfl_xor_sync(0xffffffffu, acc0, 2);
        acc1 += __shfl_xor_sync(0xffffffffu, acc1, 1);
        acc1 += __shfl_xor_sync(0xffffffffu, acc1, 2);
        if (tg == 0) {
            sPart[r0l * 2 + nh]       = acc0;
            sPart[(r0l + 8) * 2 + nh] = acc1;
        }
    }
    __syncthreads();

    if (tid < TILE_M) {
        float x = sPart[tid * 2] + sPart[tid * 2 + 1] + __ldg(b2);
        out[row0 + tid] = 1.f / (1.f + __expf(-x));
    }
}

extern "C" void kernel_launch(void* const* d_in, const int* in_sizes, int n_in,
                              void* d_out, int out_size) {
    const int*   user_ids      = (const int*)d_in[0];
    const int*   item_ids      = (const int*)d_in[1];
    const int*   sparse        = (const int*)d_in[2];
    const float* user_emb      = (const float*)d_in[3];
    const float* item_emb      = (const float*)d_in[4];
    const float* sparse_tables = (const float*)d_in[5];
    const float* W1            = (const float*)d_in[6];
    const float* b1            = (const float*)d_in[7];
    const float* W2            = (const float*)d_in[8];
    const float* b2            = (const float*)d_in[9];
    float* out = (float*)d_out;

    cudaFuncSetAttribute(dlrm_fused_kernel,
                         cudaFuncAttributeMaxDynamicSharedMemorySize, SMEM_TOTAL);

    prep_w1frag<<<(NFEAT * 4096 + 255) / 256, 256>>>(W1);
    dlrm_fused_kernel<<<BATCH / TILE_M, NTH, SMEM_TOTAL>>>(
        user_ids, item_ids, sparse, user_emb, item_emb, sparse_tables,
        b1, W2, b2, out);
}

// round 12
// speedup vs baseline: 1.7995x; 1.7995x over previous
#include <cuda_runtime.h>
#include <cuda_bf16.h>
#include <cstdint>
#include <cstddef>

// ---------------- Problem constants ----------------
#define BATCH    16384
#define EMB      64
#define NSP      26
#define NFEAT    28            // user + item + 26 sparse
#define KDIM     1792
#define NDIM     128
#define SPVOC    100000
#define TILE_M   64
#define NTH      256           // 8 warps: kg(2) x rg(2) x nh(2)
#define A_ROW_B  160           // bf16 row: 64B data + pad -> bank-perfect LDS.64
#define A_SLOT_B (16 * A_ROW_B)          // 2560 B per 16-row m-tile
#define A_STAGE_B (2 * A_SLOT_B)         // 2 m-tiles per (kg,rg) stage = 5120
#define B_SLOT_B 5120                    // [kk][lane][80B]: 64B data + 16B pad
#define X_STR    132

#define OFF_A    0
#define SZ_A     (4 * 2 * A_STAGE_B)             // 4 pga x 2 stages = 40960
#define OFF_B    SZ_A
#define SZ_B     (4 * 2 * B_SLOT_B)              // 4 pgb x 2 stages = 40960
#define OFF_IDX  (OFF_B + SZ_B)                  // 81920
#define SZ_IDX   (TILE_M * NFEAT * 4)            // 7168
#define OFF_PART (OFF_IDX + SZ_IDX)              // 89088
#define SMEM_TOTAL (OFF_PART + TILE_M * 2 * 4)   // 89600  (2 CTAs: 179200 OK)

// W1 pre-packed, padded to the exact SMEM slot image (cp.async copies raw bytes):
// u32 index = (((f*4 + pgb)*2 + kk)*32 + lane)*20 + w   (w<16 data, w>=16 pad)
// w = nt*2 + j ; value = pack_bf16(W1[k][n], W1[k+1][n])
// n = nh*64 + nt*8 + (lane>>2) ; k = f*64 + kg*32 + kk*16 + (lane&3)*2 + j*8
__device__ uint32_t g_W1fragP[NFEAT * 4 * 2 * 32 * 20];   // 573440 B

__global__ void prep_w1frag(const float* __restrict__ W1) {
    int i = blockIdx.x * blockDim.x + threadIdx.x;
    if (i >= NFEAT * 4 * 2 * 32 * 16) return;
    int w    = i & 15;
    int nt   = w >> 1;
    int j    = w & 1;
    int lane = (i >> 4) & 31;
    int kk   = (i >> 9) & 1;
    int pgb  = (i >> 10) & 3;
    int f    = i >> 12;
    int kg = pgb >> 1, nh = pgb & 1;
    int n = nh * 64 + nt * 8 + (lane >> 2);
    int k = f * 64 + kg * 32 + kk * 16 + (lane & 3) * 2 + j * 8;
    __nv_bfloat162 h = __floats2bfloat162_rn(W1[(size_t)k * NDIM + n],
                                             W1[(size_t)(k + 1) * NDIM + n]);
    g_W1fragP[(size_t)((((f * 4 + pgb) * 2 + kk) * 32 + lane) * 20 + w)] = *(uint32_t*)&h;
}

// ---------------- PTX helpers ----------------
__device__ __forceinline__ void cpa16ca(uint32_t s, const void* g) {
    asm volatile("cp.async.ca.shared.global [%0], [%1], 16;\n" :: "r"(s), "l"(g));
}
__device__ __forceinline__ void cpa_commit() {
    asm volatile("cp.async.commit_group;\n" ::: "memory");
}
__device__ __forceinline__ void cpa_wait0() {
    asm volatile("cp.async.wait_group 0;\n" ::: "memory");
}
__device__ __forceinline__ void barx(int id) {
    asm volatile("bar.sync %0, 64;" :: "r"(id) : "memory");
}
__device__ __forceinline__ uint32_t pack_bf16x2(float x, float y) {
    __nv_bfloat162 h = __floats2bfloat162_rn(x, y);
    return *(uint32_t*)&h;
}

__global__ __launch_bounds__(NTH, 2) void dlrm_fused_kernel(
    const int*   __restrict__ user_ids,
    const int*   __restrict__ item_ids,
    const int*   __restrict__ sparse,
    const float* __restrict__ user_emb,
    const float* __restrict__ item_emb,
    const float* __restrict__ sparse_tables,
    const float* __restrict__ b1,
    const float* __restrict__ W2,
    const float* __restrict__ b2,
    float*       __restrict__ out)
{
    extern __shared__ __align__(16) char smem_raw[];
    int*   sIdx  = (int*)(smem_raw + OFF_IDX);
    float* sPart = (float*)(smem_raw + OFF_PART);
    float* sX    = (float*)(smem_raw + OFF_A);    // reused post-mainloop (33792 < 81920)

    const uint32_t sb = (uint32_t)__cvta_generic_to_shared(smem_raw);

    const int tid  = threadIdx.x;
    const int warp = tid >> 5;
    const int lane = tid & 31;
    const int row0 = blockIdx.x * TILE_M;

    const int g   = lane >> 2;          // 0..7
    const int tg  = lane & 3;           // 0..3
    const int kg  = warp >> 2;          // k half (2 k16-steps)
    const int rg  = (warp >> 1) & 1;    // row group (32 rows = 2 m-tiles)
    const int nh  = warp & 1;           // n half (64 cols)
    const int pga = kg * 2 + rg;        // A share group (nh-pair)
    const int pgb = kg * 2 + nh;        // B share group (rg-pair)

    const uint32_t aGrp = sb + OFF_A + pga * (2 * A_STAGE_B);
    const uint32_t bGrp = sb + OFF_B + pgb * (2 * B_SLOT_B);

    // ---- Preload all 64x28 indices into SMEM (one round trip)
    #pragma unroll
    for (int j = 0; j < 7; ++j) {
        int linear = tid + j * NTH;          // < 1792
        int r = linear / NFEAT;
        int f = linear - r * NFEAT;
        int v;
        if (f == 0)      v = __ldg(user_ids + row0 + r);
        else if (f == 1) v = __ldg(item_ids + row0 + r);
        else             v = __ldg(sparse + (size_t)(row0 + r) * NSP + (f - 2));
        sIdx[r * NFEAT + f] = v;
    }
    __syncthreads();

    // accumulators: 2 m-tiles x 8 n-tiles x 4 (K-half partials)
    float c[2][8][4];
    #pragma unroll
    for (int mt = 0; mt < 2; ++mt)
        #pragma unroll
        for (int nt = 0; nt < 8; ++nt) {
            c[mt][nt][0] = 0.f; c[mt][nt][1] = 0.f;
            c[mt][nt][2] = 0.f; c[mt][nt][3] = 0.f;
        }

    // ---- A gather: nh-pair (64 thr) covers 32 rows x 64B (one kk block each).
    //      thread: row = pairLane>>1, kk-block = pairLane&1 (16 floats = 4 float4).
    const int pairLane = nh * 32 + lane;     // 0..63
    const int arow = pairLane >> 1;          // 0..31
    const int akk  = pairLane & 1;           // which k16 block of this kg-half
    float4 abuf[4];
    auto ldg_feat = [&](int f) {
        int idx = sIdx[(rg * 32 + arow) * NFEAT + f];
        const float* src;
        if (f == 0)      src = user_emb + (size_t)idx * EMB;
        else if (f == 1) src = item_emb + (size_t)idx * EMB;
        else             src = sparse_tables + ((size_t)(f - 2) * SPVOC + (size_t)idx) * EMB;
        const float4* s4 = (const float4*)(src + kg * 32 + akk * 16);
        abuf[0] = __ldg(s4 + 0);
        abuf[1] = __ldg(s4 + 1);
        abuf[2] = __ldg(s4 + 2);
        abuf[3] = __ldg(s4 + 3);
    };
    // permuted STS: unit u in kk block -> byte pos (u<4 ? 2u : 2u-7)*4
    auto sts_feat = [&](int f) {
        const int mt  = arow >> 4;
        const int r16 = arow & 15;
        uint32_t base = aGrp + (f & 1) * (2 * A_STAGE_B - A_STAGE_B) * 0   // placeholder
                      + (f & 1) * A_STAGE_B * 2;                            // placeholder
        // stage layout: aGrp + stage*A_STAGE_B... (see below, computed cleanly)
        base = aGrp + (f & 1) * A_STAGE_B + mt * A_SLOT_B + r16 * A_ROW_B + akk * 32;
        #pragma unroll
        for (int cc = 0; cc < 4; ++cc) {     // chunk cc -> units 2cc, 2cc+1
            float4 v = abuf[cc];
            uint32_t u0 = pack_bf16x2(v.x, v.y);
            uint32_t u1 = pack_bf16x2(v.z, v.w);
            int p0 = (cc < 2) ? cc * 4 : (cc - 2) * 4 + 1;   // 0,4,1,5
            asm volatile("st.shared.b32 [%0], %1;" :: "r"(base + p0 * 4), "r"(u0) : "memory");
            asm volatile("st.shared.b32 [%0], %1;" :: "r"(base + p0 * 4 + 8), "r"(u1) : "memory");
        }
    };

    // ---- B cp.async (.ca): rg-pair fills its (kg,nh) 5120B slot, 5 chunks/thread
    auto cpa_b = [&](int f) {
        uint32_t bslot = bGrp + (f & 1) * B_SLOT_B;
        const char* src = (const char*)g_W1fragP + (size_t)(f * 4 + pgb) * B_SLOT_B;
        const int pl = rg * 32 + lane;       // 0..63 within rg-pair
        #pragma unroll
        for (int jj = 0; jj < 5; ++jj) {
            int off = (pl + jj * 64) * 16;
            cpa16ca(bslot + off, src + off);
        }
    };

    // ---- prologue
    ldg_feat(0);
    cpa_b(0); cpa_commit();

    // ---- mainloop: decoupled, pairwise named barriers only
    #pragma unroll 1
    for (int f = 0; f < NFEAT; ++f) {
        cpa_wait0();                   // my B(f) chunks arrived
        sts_feat(f);                   // stage A(f) bf16 (stage f&1)
        barx(1 + pga);                 // nh-sibling staged A(f); old reads done
        barx(5 + pgb);                 // rg-sibling's B(f) complete + visible
        if (f + 1 < NFEAT) {
            cpa_b(f + 1); cpa_commit();
            ldg_feat(f + 1);
        }

        const uint32_t as0 = aGrp + (f & 1) * A_STAGE_B;
        const uint32_t bs  = bGrp + (f & 1) * B_SLOT_B;

        #pragma unroll
        for (int kk = 0; kk < 2; ++kk) {
            uint32_t a[2][4];
            #pragma unroll
            for (int mt = 0; mt < 2; ++mt) {
                uint32_t r0 = as0 + mt * A_SLOT_B + g * A_ROW_B + kk * 32 + tg * 8;
                asm volatile("ld.shared.v2.b32 {%0,%1}, [%2];"
                             : "=r"(a[mt][0]), "=r"(a[mt][2]) : "r"(r0));
                asm volatile("ld.shared.v2.b32 {%0,%1}, [%2];"
                             : "=r"(a[mt][1]), "=r"(a[mt][3]) : "r"(r0 + 8 * A_ROW_B));
            }
            uint32_t bb[16];
            {
                uint32_t bbase = bs + kk * 2560 + lane * 80;
                asm volatile("ld.shared.v4.b32 {%0,%1,%2,%3}, [%4];"
                             : "=r"(bb[0]), "=r"(bb[1]), "=r"(bb[2]), "=r"(bb[3])
                             : "r"(bbase));
                asm volatile("ld.shared.v4.b32 {%0,%1,%2,%3}, [%4];"
                             : "=r"(bb[4]), "=r"(bb[5]), "=r"(bb[6]), "=r"(bb[7])
                             : "r"(bbase + 16));
                asm volatile("ld.shared.v4.b32 {%0,%1,%2,%3}, [%4];"
                             : "=r"(bb[8]), "=r"(bb[9]), "=r"(bb[10]), "=r"(bb[11])
                             : "r"(bbase + 32));
                asm volatile("ld.shared.v4.b32 {%0,%1,%2,%3}, [%4];"
                             : "=r"(bb[12]), "=r"(bb[13]), "=r"(bb[14]), "=r"(bb[15])
                             : "r"(bbase + 48));
            }
            #pragma unroll
            for (int nt = 0; nt < 8; ++nt) {
                #pragma unroll
                for (int mt = 0; mt < 2; ++mt) {
                    asm volatile(
                        "mma.sync.aligned.m16n8k16.row.col.f32.bf16.bf16.f32 "
                        "{%0,%1,%2,%3}, {%4,%5,%6,%7}, {%8,%9}, {%0,%1,%2,%3};\n"
                        : "+f"(c[mt][nt][0]), "+f"(c[mt][nt][1]),
                          "+f"(c[mt][nt][2]), "+f"(c[mt][nt][3])
                        : "r"(a[mt][0]), "r"(a[mt][1]), "r"(a[mt][2]), "r"(a[mt][3]),
                          "r"(bb[nt * 2]), "r"(bb[nt * 2 + 1]));
                }
            }
        }
    }

    // ---- K-group reduction (ReLU needs full sum): kg1 stores, kg0 reduces
    __syncthreads();
    if (kg == 1) {
        #pragma unroll
        for (int mt = 0; mt < 2; ++mt)
            #pragma unroll
            for (int nt = 0; nt < 8; ++nt) {
                int r0l = rg * 32 + mt * 16 + g;
                int col = nh * 64 + nt * 8 + 2 * tg;
                sX[r0l * X_STR + col]           = c[mt][nt][0];
                sX[r0l * X_STR + col + 1]       = c[mt][nt][1];
                sX[(r0l + 8) * X_STR + col]     = c[mt][nt][2];
                sX[(r0l + 8) * X_STR + col + 1] = c[mt][nt][3];
            }
    }
    __syncthreads();

    if (kg == 0) {
        #pragma unroll
        for (int mt = 0; mt < 2; ++mt) {
            float acc0 = 0.f, acc1 = 0.f;
            int r0l = rg * 32 + mt * 16 + g;
            #pragma unroll
            for (int nt = 0; nt < 8; ++nt) {
                int n0 = nh * 64 + nt * 8 + 2 * tg;
                float h0 = c[mt][nt][0] + sX[r0l * X_STR + n0];
                float h1 = c[mt][nt][1] + sX[r0l * X_STR + n0 + 1];
                float h2 = c[mt][nt][2] + sX[(r0l + 8) * X_STR + n0];
                float h3 = c[mt][nt][3] + sX[(r0l + 8) * X_STR + n0 + 1];
                float bias0 = __ldg(b1 + n0);
                float bias1 = __ldg(b1 + n0 + 1);
                float w0 = __ldg(W2 + n0);
                float w1 = __ldg(W2 + n0 + 1);
                acc0 += fmaxf(h0 + bias0, 0.f) * w0;
                acc0 += fmaxf(h1 + bias1, 0.f) * w1;
                acc1 += fmaxf(h2 + bias0, 0.f) * w0;
                acc1 += fmaxf(h3 + bias1, 0.f) * w1;
            }
            acc0 += __shfl_xor_sync(0xffffffffu, acc0, 1);
            acc0 += __shfl_xor_sync(0xffffffffu, acc0, 2);
            acc1 += __shfl_xor_sync(0xffffffffu, acc1, 1);
            acc1 += __shfl_xor_sync(0xffffffffu, acc1, 2);
            if (tg == 0) {
                sPart[r0l * 2 + nh]       = acc0;
                sPart[(r0l + 8) * 2 + nh] = acc1;
            }
        }
    }
    __syncthreads();

    if (tid < TILE_M) {
        float x = sPart[tid * 2] + sPart[tid * 2 + 1] + __ldg(b2);
        out[row0 + tid] = 1.f / (1.f + __expf(-x));
    }
}

extern "C" void kernel_launch(void* const* d_in, const int* in_sizes, int n_in,
                              void* d_out, int out_size) {
    const int*   user_ids      = (const int*)d_in[0];
    const int*   item_ids      = (const int*)d_in[1];
    const int*   sparse        = (const int*)d_in[2];
    const float* user_emb      = (const float*)d_in[3];
    const float* item_emb      = (const float*)d_in[4];
    const float* sparse_tables = (const float*)d_in[5];
    const float* W1            = (const float*)d_in[6];
    const float* b1            = (const float*)d_in[7];
    const float* W2            = (const float*)d_in[8];
    const float* b2            = (const float*)d_in[9];
    float* out = (float*)d_out;

    cudaFuncSetAttribute(dlrm_fused_kernel,
                         cudaFuncAttributeMaxDynamicSharedMemorySize, SMEM_TOTAL);

    prep_w1frag<<<(NFEAT * 4 * 2 * 32 * 16 + 255) / 256, 256>>>(W1);
    dlrm_fused_kernel<<<BATCH / TILE_M, NTH, SMEM_TOTAL>>>(
        user_ids, item_ids, sparse, user_emb, item_emb, sparse_tables,
        b1, W2, b2, out);
}

// round 13
// speedup vs baseline: 2.2593x; 1.2555x over previous
#include <cuda_runtime.h>
#include <cuda_bf16.h>
#include <cstdint>
#include <cstddef>

// ---------------- Problem constants ----------------
#define BATCH    16384
#define EMB      64
#define NSP      26
#define NFEAT    28            // user + item + 26 sparse
#define KDIM     1792
#define NDIM     128
#define SPVOC    100000
#define TILE_M   64
#define NTH      256           // 8 warps: kg(2) x rg(2) x nh(2)
#define NASTG    2             // A stages (register-staged, double buffer)
#define NBSTG    3             // B cp.async ring stages
#define A_ROW_B  80            // bf16 row: 64B data + 16B pad; g*80%128 all distinct
#define A_SLOT_B (32 * A_ROW_B)          // 2560 B per (kg,rg) stage (32 rows)
#define B_SLOT_B 4096                    // [kk][ntp][lane][16B]
#define X_STR    132

#define OFF_A    0
#define SZ_A     (4 * NASTG * A_SLOT_B)          // 20480
#define OFF_B    SZ_A
#define SZ_B     (4 * NBSTG * B_SLOT_B)          // 49152
#define OFF_IDX  (OFF_B + SZ_B)                  // 69632
#define SZ_IDX   (TILE_M * NFEAT * 4)            // 7168
#define OFF_PART (OFF_IDX + SZ_IDX)              // 76800
#define SMEM_TOTAL (OFF_PART + TILE_M * 2 * 4)   // 77312 (x2 CTA = 154624 OK)

// W1 pre-packed in v4-friendly mma B-fragment order:
// u32 idx = ((((f*4 + pgb)*2 + kk)*4 + ntp)*32 + lane)*4 + w
// w = ntl*2 + j ; nt = ntp*2 + ntl
// val = pack_bf16(W1[k][n], W1[k+1][n]); n = nh*64+nt*8+(lane>>2);
// k = f*64 + kg*32 + kk*16 + (lane&3)*2 + j*8
__device__ uint32_t g_W1frag[NFEAT * 4096];   // 448 KB

__global__ void prep_w1frag(const float* __restrict__ W1) {
    int i = blockIdx.x * blockDim.x + threadIdx.x;
    if (i >= NFEAT * 4096) return;
    int w    = i & 3;
    int ntl  = w >> 1;
    int j    = w & 1;
    int lane = (i >> 2) & 31;
    int ntp  = (i >> 7) & 3;
    int kk   = (i >> 9) & 1;
    int pgb  = (i >> 10) & 3;
    int f    = i >> 12;
    int kg = pgb >> 1, nh = pgb & 1;
    int nt = ntp * 2 + ntl;
    int n = nh * 64 + nt * 8 + (lane >> 2);
    int k = f * 64 + kg * 32 + kk * 16 + (lane & 3) * 2 + j * 8;
    __nv_bfloat162 h = __floats2bfloat162_rn(W1[(size_t)k * NDIM + n],
                                             W1[(size_t)(k + 1) * NDIM + n]);
    g_W1frag[i] = *(uint32_t*)&h;
}

// ---------------- PTX helpers ----------------
__device__ __forceinline__ void cpa16(uint32_t s, const void* g) {
    asm volatile("cp.async.ca.shared.global [%0], [%1], 16;\n" :: "r"(s), "l"(g));
}
__device__ __forceinline__ void cpa_commit() {
    asm volatile("cp.async.commit_group;\n" ::: "memory");
}
__device__ __forceinline__ void cpa_wait1() {
    asm volatile("cp.async.wait_group 1;\n" ::: "memory");
}
__device__ __forceinline__ void barx(int id) {
    asm volatile("bar.sync %0, 64;" :: "r"(id) : "memory");
}
__device__ __forceinline__ uint32_t pack_bf16x2(float x, float y) {
    __nv_bfloat162 h = __floats2bfloat162_rn(x, y);
    return *(uint32_t*)&h;
}

__global__ __launch_bounds__(NTH, 2) void dlrm_fused_kernel(
    const int*   __restrict__ user_ids,
    const int*   __restrict__ item_ids,
    const int*   __restrict__ sparse,
    const float* __restrict__ user_emb,
    const float* __restrict__ item_emb,
    const float* __restrict__ sparse_tables,
    const float* __restrict__ b1,
    const float* __restrict__ W2,
    const float* __restrict__ b2,
    float*       __restrict__ out)
{
    extern __shared__ __align__(16) char smem_raw[];
    int*   sIdx  = (int*)(smem_raw + OFF_IDX);
    float* sPart = (float*)(smem_raw + OFF_PART);
    float* sX    = (float*)(smem_raw + OFF_A);    // reused post-mainloop (33792 < 69632)

    const uint32_t sb = (uint32_t)__cvta_generic_to_shared(smem_raw);

    const int tid  = threadIdx.x;
    const int warp = tid >> 5;
    const int lane = tid & 31;
    const int row0 = blockIdx.x * TILE_M;

    const int g   = lane >> 2;          // 0..7
    const int tg  = lane & 3;           // 0..3
    const int kg  = warp >> 2;          // k half (2 k16-steps)
    const int rg  = (warp >> 1) & 1;    // row group (32 rows = 2 m-tiles)
    const int nh  = warp & 1;           // n half (64 cols)
    const int pga = kg * 2 + rg;        // A share group (nh-pair)
    const int pgb = kg * 2 + nh;        // B share group (rg-pair)

    const uint32_t aGrp = sb + OFF_A + pga * (NASTG * A_SLOT_B);
    const uint32_t bGrp = sb + OFF_B + pgb * (NBSTG * B_SLOT_B);

    // ---- Preload all 64x28 indices into SMEM (one round trip)
    #pragma unroll
    for (int j = 0; j < 7; ++j) {
        int linear = tid + j * NTH;          // < 1792
        int r = linear / NFEAT;
        int f = linear - r * NFEAT;
        int v;
        if (f == 0)      v = __ldg(user_ids + row0 + r);
        else if (f == 1) v = __ldg(item_ids + row0 + r);
        else             v = __ldg(sparse + (size_t)(row0 + r) * NSP + (f - 2));
        sIdx[r * NFEAT + f] = v;
    }
    __syncthreads();

    // accumulators: 2 m-tiles x 8 n-tiles x 4 (K-half partials)
    float c[2][8][4];
    #pragma unroll
    for (int mt = 0; mt < 2; ++mt)
        #pragma unroll
        for (int nt = 0; nt < 8; ++nt) {
            c[mt][nt][0] = 0.f; c[mt][nt][1] = 0.f;
            c[mt][nt][2] = 0.f; c[mt][nt][3] = 0.f;
        }

    // ---- A gather: nh-pair (64 thr) covers 32 rows x 64B (one k16 block each).
    //      thread: row = pairLane>>1 (0..31), akk = pairLane&1 -> 16 floats.
    const int pairLane = nh * 32 + lane;
    const int arow = pairLane >> 1;
    const int akk  = pairLane & 1;
    float4 abuf[4];                        // 1-ahead register buffer (16 regs)
    auto ldg_feat = [&](int f) {
        int idx = sIdx[(rg * 32 + arow) * NFEAT + f];
        const float* src;
        if (f == 0)      src = user_emb + (size_t)idx * EMB;
        else if (f == 1) src = item_emb + (size_t)idx * EMB;
        else             src = sparse_tables + ((size_t)(f - 2) * SPVOC + (size_t)idx) * EMB;
        const float4* s4 = (const float4*)(src + kg * 32 + akk * 16);
        abuf[0] = __ldg(s4 + 0);
        abuf[1] = __ldg(s4 + 1);
        abuf[2] = __ldg(s4 + 2);
        abuf[3] = __ldg(s4 + 3);
    };
    // stage bf16, LINEAR unit order: unit u (k = akk*16 + 2u) at byte u*4
    auto sts_feat = [&](int f) {
        uint32_t base = aGrp + (f & 1) * A_SLOT_B + arow * A_ROW_B + akk * 32;
        uint32_t u0 = pack_bf16x2(abuf[0].x, abuf[0].y);
        uint32_t u1 = pack_bf16x2(abuf[0].z, abuf[0].w);
        uint32_t u2 = pack_bf16x2(abuf[1].x, abuf[1].y);
        uint32_t u3 = pack_bf16x2(abuf[1].z, abuf[1].w);
        uint32_t u4 = pack_bf16x2(abuf[2].x, abuf[2].y);
        uint32_t u5 = pack_bf16x2(abuf[2].z, abuf[2].w);
        uint32_t u6 = pack_bf16x2(abuf[3].x, abuf[3].y);
        uint32_t u7 = pack_bf16x2(abuf[3].z, abuf[3].w);
        asm volatile("st.shared.v4.b32 [%0], {%1,%2,%3,%4};"
                     :: "r"(base), "r"(u0), "r"(u1), "r"(u2), "r"(u3) : "memory");
        asm volatile("st.shared.v4.b32 [%0], {%1,%2,%3,%4};"
                     :: "r"(base + 16), "r"(u4), "r"(u5), "r"(u6), "r"(u7) : "memory");
    };

    // ---- B cp.async: rg-pair (64 thr) fills its (kg,nh) 4096B slot, 4 chunks/thread
    auto cpa_b = [&](int f) {
        uint32_t bslot = bGrp + (f % NBSTG) * B_SLOT_B;
        const char* src = (const char*)g_W1frag + (size_t)(f * 4 + pgb) * B_SLOT_B;
        const int pl = rg * 32 + lane;
        #pragma unroll
        for (int jj = 0; jj < 4; ++jj) {
            int off = (pl + jj * 64) * 16;
            cpa16(bslot + off, src + off);
        }
    };

    // ---- prologue: A(0) in regs; B stages 0,1 in flight
    ldg_feat(0);
    cpa_b(0); cpa_commit();
    cpa_b(1); cpa_commit();

    // ---- mainloop: decoupled, pairwise named barriers only
    #pragma unroll 1
    for (int f = 0; f < NFEAT; ++f) {
        sts_feat(f);                   // stage A(f) bf16 into slot f&1
        if (f + 1 < NFEAT) ldg_feat(f + 1);   // refill regs (covered by mma phase)
        cpa_wait1();                   // B(f) resident (B(f+1) may fly)
        barx(1 + pga);                 // nh-sibling staged A(f); its f-2 reads done
        barx(5 + pgb);                 // rg-sibling's B(f) complete + visible
        if (f + 2 < NFEAT) cpa_b(f + 2);
        cpa_commit();                  // uniform group cadence

        const uint32_t as = aGrp + (f & 1) * A_SLOT_B;
        const uint32_t bs = bGrp + (f % NBSTG) * B_SLOT_B;

        #pragma unroll
        for (int kk = 0; kk < 2; ++kk) {
            uint32_t a[2][4];
            #pragma unroll
            for (int mt = 0; mt < 2; ++mt) {
                uint32_t r0 = as + (mt * 16 + g) * A_ROW_B + kk * 32 + tg * 4;
                asm volatile("ld.shared.b32 %0, [%1];" : "=r"(a[mt][0]) : "r"(r0));
                asm volatile("ld.shared.b32 %0, [%1];" : "=r"(a[mt][2]) : "r"(r0 + 16));
                asm volatile("ld.shared.b32 %0, [%1];" : "=r"(a[mt][1]) : "r"(r0 + 8 * A_ROW_B));
                asm volatile("ld.shared.b32 %0, [%1];" : "=r"(a[mt][3]) : "r"(r0 + 8 * A_ROW_B + 16));
            }
            const uint32_t bk = bs + kk * 2048 + lane * 16;
            #pragma unroll
            for (int ntp = 0; ntp < 4; ++ntp) {
                uint32_t bb0, bb1, bb2, bb3;
                asm volatile("ld.shared.v4.b32 {%0,%1,%2,%3}, [%4];"
                             : "=r"(bb0), "=r"(bb1), "=r"(bb2), "=r"(bb3)
                             : "r"(bk + ntp * 512));
                #pragma unroll
                for (int mt = 0; mt < 2; ++mt) {
                    asm volatile(
                        "mma.sync.aligned.m16n8k16.row.col.f32.bf16.bf16.f32 "
                        "{%0,%1,%2,%3}, {%4,%5,%6,%7}, {%8,%9}, {%0,%1,%2,%3};\n"
                        : "+f"(c[mt][ntp * 2][0]), "+f"(c[mt][ntp * 2][1]),
                          "+f"(c[mt][ntp * 2][2]), "+f"(c[mt][ntp * 2][3])
                        : "r"(a[mt][0]), "r"(a[mt][1]), "r"(a[mt][2]), "r"(a[mt][3]),
                          "r"(bb0), "r"(bb1));
                    asm volatile(
                        "mma.sync.aligned.m16n8k16.row.col.f32.bf16.bf16.f32 "
                        "{%0,%1,%2,%3}, {%4,%5,%6,%7}, {%8,%9}, {%0,%1,%2,%3};\n"
                        : "+f"(c[mt][ntp * 2 + 1][0]), "+f"(c[mt][ntp * 2 + 1][1]),
                          "+f"(c[mt][ntp * 2 + 1][2]), "+f"(c[mt][ntp * 2 + 1][3])
                        : "r"(a[mt][0]), "r"(a[mt][1]), "r"(a[mt][2]), "r"(a[mt][3]),
                          "r"(bb2), "r"(bb3));
                }
            }
        }
    }

    // ---- K-group reduction (ReLU needs full sum): kg1 stores, kg0 reduces
    __syncthreads();                  // all ring reads done; reuse region as sX
    if (kg == 1) {
        #pragma unroll
        for (int mt = 0; mt < 2; ++mt)
            #pragma unroll
            for (int nt = 0; nt < 8; ++nt) {
                int r0l = rg * 32 + mt * 16 + g;
                int col = nh * 64 + nt * 8 + 2 * tg;
                sX[r0l * X_STR + col]           = c[mt][nt][0];
                sX[r0l * X_STR + col + 1]       = c[mt][nt][1];
                sX[(r0l + 8) * X_STR + col]     = c[mt][nt][2];
                sX[(r0l + 8) * X_STR + col + 1] = c[mt][nt][3];
            }
    }
    __syncthreads();

    if (kg == 0) {
        #pragma unroll
        for (int mt = 0; mt < 2; ++mt) {
            float acc0 = 0.f, acc1 = 0.f;
            int r0l = rg * 32 + mt * 16 + g;
            #pragma unroll
            for (int nt = 0; nt < 8; ++nt) {
                int n0 = nh * 64 + nt * 8 + 2 * tg;
                float h0 = c[mt][nt][0] + sX[r0l * X_STR + n0];
                float h1 = c[mt][nt][1] + sX[r0l * X_STR + n0 + 1];
                float h2 = c[mt][nt][2] + sX[(r0l + 8) * X_STR + n0];
                float h3 = c[mt][nt][3] + sX[(r0l + 8) * X_STR + n0 + 1];
                float bias0 = __ldg(b1 + n0);
                float bias1 = __ldg(b1 + n0 + 1);
                float w0 = __ldg(W2 + n0);
                float w1 = __ldg(W2 + n0 + 1);
                acc0 += fmaxf(h0 + bias0, 0.f) * w0;
                acc0 += fmaxf(h1 + bias1, 0.f) * w1;
                acc1 += fmaxf(h2 + bias0, 0.f) * w0;
                acc1 += fmaxf(h3 + bias1, 0.f) * w1;
            }
            acc0 += __shfl_xor_sync(0xffffffffu, acc0, 1);
            acc0 += __shfl_xor_sync(0xffffffffu, acc0, 2);
            acc1 += __shfl_xor_sync(0xffffffffu, acc1, 1);
            acc1 += __shfl_xor_sync(0xffffffffu, acc1, 2);
            if (tg == 0) {
                sPart[r0l * 2 + nh]       = acc0;
                sPart[(r0l + 8) * 2 + nh] = acc1;
            }
        }
    }
    __syncthreads();

    if (tid < TILE_M) {
        float x = sPart[tid * 2] + sPart[tid * 2 + 1] + __ldg(b2);
        out[row0 + tid] = 1.f / (1.f + __expf(-x));
    }
}

extern "C" void kernel_launch(void* const* d_in, const int* in_sizes, int n_in,
                              void* d_out, int out_size) {
    const int*   user_ids      = (const int*)d_in[0];
    const int*   item_ids      = (const int*)d_in[1];
    const int*   sparse        = (const int*)d_in[2];
    const float* user_emb      = (const float*)d_in[3];
    const float* item_emb      = (const float*)d_in[4];
    const float* sparse_tables = (const float*)d_in[5];
    const float* W1            = (const float*)d_in[6];
    const float* b1            = (const float*)d_in[7];
    const float* W2            = (const float*)d_in[8];
    const float* b2            = (const float*)d_in[9];
    float* out = (float*)d_out;

    cudaFuncSetAttribute(dlrm_fused_kernel,
                         cudaFuncAttributeMaxDynamicSharedMemorySize, SMEM_TOTAL);

    prep_w1frag<<<(NFEAT * 4096 + 255) / 256, 256>>>(W1);
    dlrm_fused_kernel<<<BATCH / TILE_M, NTH, SMEM_TOTAL>>>(
        user_ids, item_ids, sparse, user_emb, item_emb, sparse_tables,
        b1, W2, b2, out);
}